// round 14
// baseline (speedup 1.0000x reference)
#include <cuda_runtime.h>
#include <cuda_fp16.h>
#include <cuda_bf16.h>
#include <cstdint>
#include <cstddef>

// Problem dims
#define BN   8192
#define DK   4096
#define HN   8192
#define NEXP 2

#define XSCALE 256.0f
#define WSCALE 1024.0f
#define INV_S  (1.0f / (256.0f * 1024.0f))
#define LN4    1.3862943611198906f   // conf<0.8  <=>  |t0-t1| < ln4

// GEMM tiling: block 128x256, 512 threads (16 warps, warp tile 64x32), K=32/kt
#define TBM 128
#define TBN 256
#define TBK 32
#define KCHUNKS (DK / TBK)          // 128
#define MBLK (BN / TBM)             // 64
#define NBLK (HN / TBN)             // 32
#define GROUP_M 16
#define NCH (NBLK * 8)              // 256 col-chunks of 32

// SMEM stage layout. fp16 rows: 64B data + 16B pad (stride 80).
// int8 rows: 32B data + 16B pad (stride 48). Both strides give
// conflict-free ldmatrix (5r mod 8 / 3r mod 8 bijections).
#define XH_OFF  0                   // 128 * 80  = 10240
#define WH_OFF  10240               // 256 * 80  = 20480
#define XHQ_OFF 30720               // 128 * 48  = 6144
#define XLQ_OFF 36864               // 128 * 48  = 6144
#define WHQ_OFF 43008               // 256 * 48  = 12288
#define WLQ_OFF 55296               // 256 * 48  = 12288
#define STG_BYTES 67584
#define SOFF_B1S (2 * STG_BYTES)               // 135168 (256 floats)
#define SOFF_W2S (SOFF_B1S + 1024)             // 136192 (512 floats)
#define SMEM_TOTAL (SOFF_W2S + 2048)           // 138240

// ---------------------------------------------------------------------------
// Device scratch (static; no allocation allowed)
// ---------------------------------------------------------------------------
__device__ __half  g_xhi[(size_t)BN * DK];           // Xh = fp16(x*256)
__device__ int8_t  g_xhq[(size_t)BN * DK];           // round(Xh/16)
__device__ int8_t  g_xlq[(size_t)BN * DK];           // round(Xl*256)
__device__ __half  g_whi[(size_t)NEXP * HN * DK];    // Wh = fp16(w*1024), [e][H][D]
__device__ int8_t  g_whq[(size_t)NEXP * HN * DK];    // round(Wh)
__device__ int8_t  g_wlq[(size_t)NEXP * HN * DK];    // round(Wl*4096)
__device__ float   g_part[(size_t)NEXP * BN * NCH * 2];

// ---------------------------------------------------------------------------
// PTX helpers (baseline ISA, sm_80-era)
// ---------------------------------------------------------------------------
__device__ __forceinline__ void cp_async16(uint32_t dst, const void* src) {
    asm volatile("cp.async.cg.shared.global [%0], [%1], 16;"
                 :: "r"(dst), "l"(__cvta_generic_to_global(src)));
}
__device__ __forceinline__ void cp_commit() {
    asm volatile("cp.async.commit_group;" ::: "memory");
}
__device__ __forceinline__ void cp_wait1() {
    asm volatile("cp.async.wait_group 1;" ::: "memory");
}
__device__ __forceinline__ void cp_wait0() {
    asm volatile("cp.async.wait_group 0;" ::: "memory");
}
__device__ __forceinline__ uint32_t smem_u32(const void* p) {
    uint32_t a;
    asm("{ .reg .u64 t; cvta.to.shared.u64 t, %1; cvt.u32.u64 %0, t; }"
        : "=r"(a) : "l"(p));
    return a;
}
__device__ __forceinline__ void ldsm4(uint32_t (&r)[4], uint32_t addr) {
    asm volatile("ldmatrix.sync.aligned.m8n8.x4.shared.b16 {%0,%1,%2,%3}, [%4];"
                 : "=r"(r[0]), "=r"(r[1]), "=r"(r[2]), "=r"(r[3]) : "r"(addr));
}

#define HMMA(c, a, b0v, b1v) asm volatile( \
    "mma.sync.aligned.m16n8k16.row.col.f32.f16.f16.f32 " \
    "{%0,%1,%2,%3}, {%4,%5,%6,%7}, {%8,%9}, {%0,%1,%2,%3};" \
    : "+f"((c)[0]), "+f"((c)[1]), "+f"((c)[2]), "+f"((c)[3]) \
    : "r"((a)[0]), "r"((a)[1]), "r"((a)[2]), "r"((a)[3]), \
      "r"(b0v), "r"(b1v))

#define IMMA(c, a, b0v, b1v) asm volatile( \
    "mma.sync.aligned.m16n8k32.row.col.s32.s8.s8.s32 " \
    "{%0,%1,%2,%3}, {%4,%5,%6,%7}, {%8,%9}, {%0,%1,%2,%3};" \
    : "+r"((c)[0]), "+r"((c)[1]), "+r"((c)[2]), "+r"((c)[3]) \
    : "r"((a)[0]), "r"((a)[1]), "r"((a)[2]), "r"((a)[3]), \
      "r"(b0v), "r"(b1v))

__device__ __forceinline__ int8_t q8(float v) {
    int i = __float2int_rn(fminf(fmaxf(v, -127.0f), 127.0f));
    return (int8_t)i;
}

// ---------------------------------------------------------------------------
// Kernel 1: split x -> Xh (fp16), Xhq, Xlq (int8)
// ---------------------------------------------------------------------------
__global__ void split_x_kernel(const float* __restrict__ x) {
    size_t i = (size_t)blockIdx.x * blockDim.x + threadIdx.x;   // BN*DK/4
    float4 v = reinterpret_cast<const float4*>(x)[i];
    float a[4] = { v.x * XSCALE, v.y * XSCALE, v.z * XSCALE, v.w * XSCALE };
    __half hh[4];
    char xh8[4], xl8[4];
    #pragma unroll
    for (int k = 0; k < 4; ++k) {
        hh[k] = __float2half_rn(a[k]);
        float hf = __half2float(hh[k]);
        xh8[k] = (char)q8(hf * 0.0625f);            // Xh/16
        xl8[k] = (char)q8((a[k] - hf) * 256.0f);    // Xl*256
    }
    __half2* ph = reinterpret_cast<__half2*>(g_xhi + 4 * i);
    ph[0] = __halves2half2(hh[0], hh[1]);
    ph[1] = __halves2half2(hh[2], hh[3]);
    *reinterpret_cast<char4*>(g_xhq + 4 * i) = make_char4(xh8[0], xh8[1], xh8[2], xh8[3]);
    *reinterpret_cast<char4*>(g_xlq + 4 * i) = make_char4(xl8[0], xl8[1], xl8[2], xl8[3]);
}

// ---------------------------------------------------------------------------
// Kernel 2: split + transpose w1 -> Wh (fp16), Whq, Wlq (int8), all [H][D]
// ---------------------------------------------------------------------------
__global__ void split_w_kernel(const float* __restrict__ tw,
                               const float* __restrict__ fw) {
    __shared__ float tile[32][33];
    int e = blockIdx.z;
    const float* w = e ? fw : tw;
    __half*  ohi = g_whi + (size_t)e * HN * DK;
    int8_t*  ohq = g_whq + (size_t)e * HN * DK;
    int8_t*  olq = g_wlq + (size_t)e * HN * DK;
    int h0 = blockIdx.x * 32, d0 = blockIdx.y * 32;
    int tx = threadIdx.x, ty = threadIdx.y;
    #pragma unroll
    for (int i = ty; i < 32; i += 8)
        tile[i][tx] = w[(size_t)(d0 + i) * HN + h0 + tx];
    __syncthreads();
    #pragma unroll
    for (int i = ty; i < 32; i += 8) {
        float v = tile[tx][i] * WSCALE;
        __half hi = __float2half_rn(v);
        float hf = __half2float(hi);
        size_t o = (size_t)(h0 + i) * DK + d0 + tx;
        ohi[o] = hi;
        ohq[o] = q8(hf);                       // Wh
        olq[o] = q8((v - hf) * 4096.0f);       // Wl*4096
    }
}

// ---------------------------------------------------------------------------
// Kernel 3: hybrid GEMM — HMMA(hi*hi, f32) + IMMA(corrections, s32) + fused L2
// grid (MBLK*NBLK), 512 threads, dyn smem SMEM_TOTAL; one launch per expert
// ---------------------------------------------------------------------------
__global__ void __launch_bounds__(512, 1)
gemm_kernel(int e,
            const float* __restrict__ b1t, const float* __restrict__ b1f,
            const float* __restrict__ w2t, const float* __restrict__ w2f) {
    extern __shared__ char sm[];
    const uint32_t sb = smem_u32(sm);
    const int t    = threadIdx.x;
    const int lane = t & 31;
    const int wid  = t >> 5;

    // Grouped rasterization
    int bid = blockIdx.x;
    int grp = bid / (GROUP_M * NBLK);
    int rem = bid % (GROUP_M * NBLK);
    int mb  = grp * GROUP_M + (rem % GROUP_M);
    int nb  = rem / GROUP_M;
    const int m0 = mb * TBM;
    const int n0 = nb * TBN;

    const __half*  wh  = g_whi + (size_t)e * HN * DK;
    const int8_t*  whq = g_whq + (size_t)e * HN * DK;
    const int8_t*  wlq = g_wlq + (size_t)e * HN * DK;
    const float*   b1  = (e ? b1f : b1t) + n0;
    const float*   w2  = (e ? w2f : w2t) + (size_t)n0 * 2;

    float* b1s = reinterpret_cast<float*>(sm + SOFF_B1S);
    float* w2s = reinterpret_cast<float*>(sm + SOFF_W2S);
    if (t < TBN) b1s[t] = b1[t];
    w2s[t] = w2[t];

    // 16 warps: 2 in M (64 rows) x 8 in N (32 cols)
    const int m_off = (wid >> 3) * 64;
    const int n_off = (wid & 7) * 32;
    const int lrow  = lane & 15;
    const int lk16  = (lane >> 4) << 4;

    float    accf[4][4][4];
    int32_t  acci[4][4][4];
    #pragma unroll
    for (int i = 0; i < 4; ++i)
        #pragma unroll
        for (int j = 0; j < 4; ++j)
            #pragma unroll
            for (int r = 0; r < 4; ++r) { accf[i][j][r] = 0.0f; acci[i][j][r] = 0; }

    // Loader: 3072 x 16B chunks, 6 per thread
    auto load_stage = [&](int stage, int kt) {
        const uint32_t tb = sb + (uint32_t)stage * STG_BYTES;
        const int kkH = kt * TBK;       // halves for fp16, bytes for int8
        #pragma unroll
        for (int jj = 0; jj < 6; ++jj) {
            int c = jj * 512 + t;
            const void* src;
            uint32_t dst;
            if (c < 512) {                       // Xh fp16
                int r = c >> 2, c2 = c & 3;
                src = g_xhi + (size_t)(m0 + r) * DK + kkH + c2 * 8;
                dst = tb + XH_OFF + r * 80 + c2 * 16;
            } else if (c < 1536) {               // Wh fp16
                int rc = c - 512, r = rc >> 2, c2 = rc & 3;
                src = wh + (size_t)(n0 + r) * DK + kkH + c2 * 8;
                dst = tb + WH_OFF + r * 80 + c2 * 16;
            } else if (c < 1792) {               // Xhq int8
                int rc = c - 1536, r = rc >> 1, c2 = rc & 1;
                src = g_xhq + (size_t)(m0 + r) * DK + kkH + c2 * 16;
                dst = tb + XHQ_OFF + r * 48 + c2 * 16;
            } else if (c < 2048) {               // Xlq int8
                int rc = c - 1792, r = rc >> 1, c2 = rc & 1;
                src = g_xlq + (size_t)(m0 + r) * DK + kkH + c2 * 16;
                dst = tb + XLQ_OFF + r * 48 + c2 * 16;
            } else if (c < 2560) {               // Whq int8
                int rc = c - 2048, r = rc >> 1, c2 = rc & 1;
                src = whq + (size_t)(n0 + r) * DK + kkH + c2 * 16;
                dst = tb + WHQ_OFF + r * 48 + c2 * 16;
            } else {                             // Wlq int8
                int rc = c - 2560, r = rc >> 1, c2 = rc & 1;
                src = wlq + (size_t)(n0 + r) * DK + kkH + c2 * 16;
                dst = tb + WLQ_OFF + r * 48 + c2 * 16;
            }
            cp_async16(dst, src);
        }
        cp_commit();
    };

    load_stage(0, 0);

    const uint32_t bQoff = (uint32_t)(n_off + ((lane >> 4) << 3) + (lane & 7)) * 48
                           + (((lane >> 3) & 1) << 4);

    for (int kt = 0; kt < KCHUNKS; ++kt) {
        if (kt + 1 < KCHUNKS) { load_stage((kt + 1) & 1, kt + 1); cp_wait1(); }
        else                  { cp_wait0(); }
        __syncthreads();

        const uint32_t tb  = sb + (uint32_t)(kt & 1) * STG_BYTES;
        const uint32_t aF  = tb + XH_OFF  + (uint32_t)(m_off + lrow) * 80 + lk16;
        const uint32_t bF  = tb + WH_OFF  + (uint32_t)(n_off + lrow) * 80 + lk16;
        const uint32_t aQ  = tb + XHQ_OFF + (uint32_t)(m_off + lrow) * 48 + lk16;
        const uint32_t aQl = tb + XLQ_OFF + (uint32_t)(m_off + lrow) * 48 + lk16;
        const uint32_t bQh = tb + WHQ_OFF + bQoff;
        const uint32_t bQl = tb + WLQ_OFF + bQoff;

        // ---- IMMA pass A: Xhq * Wlq ----
        {
            uint32_t a8[4][4], b8[2][4];
            #pragma unroll
            for (int i = 0; i < 4; ++i) ldsm4(a8[i], aQ + i * (16 * 48));
            ldsm4(b8[0], bQl);
            ldsm4(b8[1], bQl + 16 * 48);
            #pragma unroll
            for (int i = 0; i < 4; ++i)
                #pragma unroll
                for (int j = 0; j < 4; ++j)
                    IMMA(acci[i][j], a8[i], b8[j >> 1][(j & 1) * 2],
                                             b8[j >> 1][(j & 1) * 2 + 1]);
        }
        // ---- HMMA ks=0: Xh * Wh ----
        {
            uint32_t af[4][4], bf[2][4];
            #pragma unroll
            for (int i = 0; i < 4; ++i) ldsm4(af[i], aF + i * (16 * 80));
            ldsm4(bf[0], bF);
            ldsm4(bf[1], bF + 16 * 80);
            #pragma unroll
            for (int i = 0; i < 4; ++i)
                #pragma unroll
                for (int j = 0; j < 4; ++j)
                    HMMA(accf[i][j], af[i], bf[j >> 1][j & 1],
                                            bf[j >> 1][2 + (j & 1)]);
        }
        // ---- IMMA pass B: Xlq * Whq ----
        {
            uint32_t a8[4][4], b8[2][4];
            #pragma unroll
            for (int i = 0; i < 4; ++i) ldsm4(a8[i], aQl + i * (16 * 48));
            ldsm4(b8[0], bQh);
            ldsm4(b8[1], bQh + 16 * 48);
            #pragma unroll
            for (int i = 0; i < 4; ++i)
                #pragma unroll
                for (int j = 0; j < 4; ++j)
                    IMMA(acci[i][j], a8[i], b8[j >> 1][(j & 1) * 2],
                                             b8[j >> 1][(j & 1) * 2 + 1]);
        }
        // ---- HMMA ks=1 ----
        {
            uint32_t af[4][4], bf[2][4];
            #pragma unroll
            for (int i = 0; i < 4; ++i) ldsm4(af[i], aF + i * (16 * 80) + 32);
            ldsm4(bf[0], bF + 32);
            ldsm4(bf[1], bF + 16 * 80 + 32);
            #pragma unroll
            for (int i = 0; i < 4; ++i)
                #pragma unroll
                for (int j = 0; j < 4; ++j)
                    HMMA(accf[i][j], af[i], bf[j >> 1][j & 1],
                                            bf[j >> 1][2 + (j & 1)]);
        }
        __syncthreads();
    }

    // Epilogue: h = relu((accf + acci/256)*INV_S + b1); dot with w2
    const int tig = lane & 3;
    #pragma unroll
    for (int i = 0; i < 4; ++i) {
        float plo0 = 0.f, plo1 = 0.f, phi0 = 0.f, phi1 = 0.f;
        #pragma unroll
        for (int j = 0; j < 4; ++j) {
            int col = n_off + j * 8 + tig * 2;
            float bb0 = b1s[col], bb1 = b1s[col + 1];
            float v0 = accf[i][j][0] + (float)acci[i][j][0] * (1.0f / 256.0f);
            float v1 = accf[i][j][1] + (float)acci[i][j][1] * (1.0f / 256.0f);
            float v2 = accf[i][j][2] + (float)acci[i][j][2] * (1.0f / 256.0f);
            float v3 = accf[i][j][3] + (float)acci[i][j][3] * (1.0f / 256.0f);
            float h0 = fmaxf(v0 * INV_S + bb0, 0.0f);
            float h1 = fmaxf(v1 * INV_S + bb1, 0.0f);
            float h2 = fmaxf(v2 * INV_S + bb0, 0.0f);
            float h3 = fmaxf(v3 * INV_S + bb1, 0.0f);
            float w00 = w2s[2 * col],     w01 = w2s[2 * col + 1];
            float w10 = w2s[2 * col + 2], w11 = w2s[2 * col + 3];
            plo0 += h0 * w00 + h1 * w10;
            plo1 += h0 * w01 + h1 * w11;
            phi0 += h2 * w00 + h3 * w10;
            phi1 += h2 * w01 + h3 * w11;
        }
        #pragma unroll
        for (int o = 1; o <= 2; o <<= 1) {
            plo0 += __shfl_xor_sync(0xFFFFFFFFu, plo0, o);
            plo1 += __shfl_xor_sync(0xFFFFFFFFu, plo1, o);
            phi0 += __shfl_xor_sync(0xFFFFFFFFu, phi0, o);
            phi1 += __shfl_xor_sync(0xFFFFFFFFu, phi1, o);
        }
        if (tig == 0) {
            int rlo = m0 + m_off + i * 16 + (lane >> 2);
            int cch = nb * 8 + (wid & 7);
            float2* dlo = reinterpret_cast<float2*>(
                g_part + (((size_t)e * BN + rlo) * NCH + cch) * 2);
            float2* dhi = reinterpret_cast<float2*>(
                g_part + (((size_t)e * BN + rlo + 8) * NCH + cch) * 2);
            *dlo = make_float2(plo0, plo1);
            *dhi = make_float2(phi0, phi1);
        }
    }
}

// ---------------------------------------------------------------------------
// Kernel 4: reduce partials + bias + confidence select (warp per row)
// ---------------------------------------------------------------------------
__global__ void reduce_kernel(const float* __restrict__ b2t,
                              const float* __restrict__ b2f,
                              float* __restrict__ out) {
    int row  = (blockIdx.x * blockDim.x + threadIdx.x) >> 5;
    int lane = threadIdx.x & 31;
    const float2* pt = reinterpret_cast<const float2*>(
        g_part + ((size_t)row) * NCH * 2);
    const float2* pf = reinterpret_cast<const float2*>(
        g_part + ((size_t)(BN + row)) * NCH * 2);
    float T0 = 0.f, T1 = 0.f, F0 = 0.f, F1 = 0.f;
    #pragma unroll
    for (int k = lane; k < NCH; k += 32) {
        float2 a = pt[k], b = pf[k];
        T0 += a.x; T1 += a.y;
        F0 += b.x; F1 += b.y;
    }
    #pragma unroll
    for (int o = 16; o > 0; o >>= 1) {
        T0 += __shfl_xor_sync(0xFFFFFFFFu, T0, o);
        T1 += __shfl_xor_sync(0xFFFFFFFFu, T1, o);
        F0 += __shfl_xor_sync(0xFFFFFFFFu, F0, o);
        F1 += __shfl_xor_sync(0xFFFFFFFFu, F1, o);
    }
    if (lane == 0) {
        T0 += b2t[0]; T1 += b2t[1];
        F0 += b2f[0]; F1 += b2f[1];
        bool low = fabsf(T0 - T1) < LN4;     // conf = sigmoid(|d|) < 0.8
        reinterpret_cast<float2*>(out)[row] =
            low ? make_float2(F0, F1) : make_float2(T0, T1);
    }
}

// ---------------------------------------------------------------------------
// Launch
// ---------------------------------------------------------------------------
extern "C" void kernel_launch(void* const* d_in, const int* in_sizes, int n_in,
                              void* d_out, int out_size) {
    const float* x    = (const float*)d_in[0];
    const float* t_w1 = (const float*)d_in[1];
    const float* t_b1 = (const float*)d_in[2];
    const float* t_w2 = (const float*)d_in[3];
    const float* t_b2 = (const float*)d_in[4];
    const float* f_w1 = (const float*)d_in[5];
    const float* f_b1 = (const float*)d_in[6];
    const float* f_w2 = (const float*)d_in[7];
    const float* f_b2 = (const float*)d_in[8];
    float* out = (float*)d_out;

    cudaFuncSetAttribute(gemm_kernel,
                         cudaFuncAttributeMaxDynamicSharedMemorySize, SMEM_TOTAL);

    split_x_kernel<<<(size_t)BN * DK / 4 / 256, 256>>>(x);
    split_w_kernel<<<dim3(HN / 32, DK / 32, 2), dim3(32, 8)>>>(t_w1, f_w1);
    gemm_kernel<<<MBLK * NBLK, 512, SMEM_TOTAL>>>(0, t_b1, f_b1, t_w2, f_w2);
    gemm_kernel<<<MBLK * NBLK, 512, SMEM_TOTAL>>>(1, t_b1, f_b1, t_w2, f_w2);
    reduce_kernel<<<dim3(BN * 32 / 256), 256>>>(t_b2, f_b2, out);
}